// round 14
// baseline (speedup 1.0000x reference)
#include <cuda_runtime.h>
#include <cuda_fp16.h>
#include <cstdint>

#define N_NODES 50000
#define N_EDGES 800000
#define R_REL 8
#define H_DIM 128
#define ROW_TILES ((N_NODES + 127) / 128)
#define SCAN_BLKS ((N_NODES + 255) / 256)
#define PAD 136
#define TILE_A (128 * PAD)
#define GEMM_SMEM (5 * TILE_A * 2)

// ---------------- scratch (device globals: allocation-free) ----------------
__device__ __half g_xWh[(size_t)R_REL * N_NODES * H_DIM];  // 102.4 MB (fits L2)
__device__ __half g_ah[(size_t)N_NODES * H_DIM];           // A operand (x, then h1, h2)
__device__ __half g_bhi[R_REL * H_DIM * H_DIM];            // [r][n][k] = W[r][k][n] hi
__device__ __half g_blo[R_REL * H_DIM * H_DIM];            // lo residual
__device__ float g_sq[R_REL * N_NODES];
__device__ float g_sk[R_REL * N_NODES];
__device__ float g_sq2[R_REL * N_NODES];
__device__ float g_sk2[R_REL * N_NODES];
__device__ float g_wq[R_REL * H_DIM];
__device__ float g_wk[R_REL * H_DIM];
__device__ float g_wq2[R_REL * H_DIM];
__device__ float g_wk2[R_REL * H_DIM];
__device__ int   g_cnt[N_NODES];
__device__ int   g_rowptr[N_NODES + 1];
__device__ int   g_cursor[N_NODES];
__device__ int   g_csr[N_EDGES];
__device__ int   g_blksum[SCAN_BLKS];
__device__ int   g_total;

__device__ __forceinline__ uint32_t smem_u32(const void* p) {
    uint32_t a;
    asm("{ .reg .u64 t; cvta.to.shared.u64 t, %1; cvt.u32.u64 %0, t; }" : "=r"(a) : "l"(p));
    return a;
}

// ---------------- CSR build ----------------
__global__ void k_zero_cnt() {
    int i = blockIdx.x * blockDim.x + threadIdx.x;
    if (i < N_NODES) g_cnt[i] = 0;
}
__global__ void k_hist(const int* __restrict__ tgt) {
    int e = blockIdx.x * blockDim.x + threadIdx.x;
    if (e < N_EDGES) atomicAdd(&g_cnt[tgt[e]], 1);
}
__global__ __launch_bounds__(256) void k_scan_blk() {
    __shared__ int sm[256];
    int tid = threadIdx.x;
    int i = blockIdx.x * 256 + tid;
    int v = (i < N_NODES) ? g_cnt[i] : 0;
    sm[tid] = v;
    __syncthreads();
#pragma unroll
    for (int off = 1; off < 256; off <<= 1) {
        int t = (tid >= off) ? sm[tid - off] : 0;
        __syncthreads();
        sm[tid] += t;
        __syncthreads();
    }
    if (i < N_NODES) g_rowptr[i] = sm[tid] - v;
    if (tid == 255) g_blksum[blockIdx.x] = sm[255];
}
__global__ __launch_bounds__(256) void k_scan_top() {
    __shared__ int sm[256];
    int tid = threadIdx.x;
    int v = (tid < SCAN_BLKS) ? g_blksum[tid] : 0;
    sm[tid] = v;
    __syncthreads();
#pragma unroll
    for (int off = 1; off < 256; off <<= 1) {
        int t = (tid >= off) ? sm[tid - off] : 0;
        __syncthreads();
        sm[tid] += t;
        __syncthreads();
    }
    if (tid < SCAN_BLKS) g_blksum[tid] = sm[tid] - v;
    if (tid == 255) g_total = sm[255];
}
__global__ __launch_bounds__(256) void k_scan_add() {
    int i = blockIdx.x * 256 + threadIdx.x;
    if (i < N_NODES) {
        int v = g_rowptr[i] + g_blksum[blockIdx.x];
        g_rowptr[i] = v;
        g_cursor[i] = v;
    }
    if (i == 0) g_rowptr[N_NODES] = g_total;
}
__global__ void k_scatter(const int* __restrict__ src, const int* __restrict__ tgt,
                          const int* __restrict__ et) {
    int e = blockIdx.x * blockDim.x + threadIdx.x;
    if (e < N_EDGES) {
        int pos = atomicAdd(&g_cursor[tgt[e]], 1);
        g_csr[pos] = (et[e] << 17) | src[e];
    }
}

// ---------------- operand conversion ----------------
__global__ void k_split_act(const float* __restrict__ act, int total4) {
    int i = blockIdx.x * blockDim.x + threadIdx.x;
    if (i >= total4) return;
    float4 v = *(const float4*)&act[i * 4];
    __half2* p = (__half2*)&g_ah[i * 4];
    p[0] = __floats2half2_rn(v.x, v.y);
    p[1] = __floats2half2_rn(v.z, v.w);
}
// B[r][n][k] = W[r][k][n], fp16 hi + residual lo
__global__ void k_split_W(const float* __restrict__ W) {
    int i = blockIdx.x * blockDim.x + threadIdx.x;   // r*16384 + n*128 + k
    if (i >= R_REL * H_DIM * H_DIM) return;
    int k = i & 127, n = (i >> 7) & 127, r = i >> 14;
    float w = W[(size_t)r * 16384 + k * 128 + n];
    __half h = __float2half_rn(w);
    g_bhi[i] = h;
    g_blo[i] = __float2half_rn(w - __half2float(h));
}
__global__ void k_split_Wl(const float* __restrict__ Wl) {
    int i = blockIdx.x * blockDim.x + threadIdx.x;
    if (i >= H_DIM * H_DIM) return;
    float w = Wl[i];
    __half h = __float2half_rn(w);
    g_bhi[i] = h;
    g_blo[i] = __float2half_rn(w - __half2float(h));
}

#define MMA_F16(d, a, b) \
    asm volatile("mma.sync.aligned.m16n8k16.row.col.f32.f16.f16.f32 " \
                 "{%0,%1,%2,%3}, {%4,%5,%6,%7}, {%8,%9}, {%0,%1,%2,%3};" \
                 : "+f"((d)[0]), "+f"((d)[1]), "+f"((d)[2]), "+f"((d)[3]) \
                 : "r"((a)[0]), "r"((a)[1]), "r"((a)[2]), "r"((a)[3]), \
                   "r"((b)[0]), "r"((b)[1]))

// ---------------- HMMA GEMM (fp16 2-term): one CTA per row-tile, all NREL relations
// A fp16 resident in smem (1 tile); B (hi/lo) double-buffered with cp.async prefetch.
// smem: A + 2x2 B tiles = 5 x 128x136 fp16 = 174 KB.
extern __shared__ __half s_dyn[];
template<int NREL, bool LIN>
__global__ __launch_bounds__(256) void k_hgemm(float* __restrict__ outp,
                                               const float* __restrict__ bias) {
    int tid = threadIdx.x;
    int wid = tid >> 5, lane = tid & 31;
    int wr = wid >> 1, wc = wid & 1;
    int rowBase = blockIdx.x * 128;

    uint32_t sA = smem_u32(&s_dyn[0]);
    uint32_t sB[2][2] = { { smem_u32(&s_dyn[TILE_A]), smem_u32(&s_dyn[2 * TILE_A]) },
                          { smem_u32(&s_dyn[3 * TILE_A]), smem_u32(&s_dyn[4 * TILE_A]) } };

    // ---- prologue: A + B[0]; then B[1] ----
#pragma unroll
    for (int t = 0; t < 8; t++) {
        int idx = t * 256 + tid;                 // 0..2047
        int ch = idx & 15;
        int row = idx >> 4;
        uint32_t dst = sA + (row * PAD + ch * 8) * 2;
        int gr = rowBase + row;
        const __half* src = g_ah + (size_t)gr * 128 + ch * 8;
        int sz = (gr < N_NODES) ? 16 : 0;
        asm volatile("cp.async.cg.shared.global [%0], [%1], 16, %2;"
                     :: "r"(dst), "l"(src), "r"(sz));
    }
#pragma unroll
    for (int t = 0; t < 16; t++) {
        int idx = t * 256 + tid;                 // 0..4095
        int ch = idx & 15;
        int row = (idx >> 4) & 127;
        int tile = idx >> 11;
        uint32_t dst = sB[0][tile] + (row * PAD + ch * 8) * 2;
        const __half* src = ((tile == 0) ? g_bhi : g_blo) + (size_t)row * 128 + ch * 8;
        asm volatile("cp.async.cg.shared.global [%0], [%1], 16;" :: "r"(dst), "l"(src));
    }
    asm volatile("cp.async.commit_group;");
    if (NREL > 1) {
#pragma unroll
        for (int t = 0; t < 16; t++) {
            int idx = t * 256 + tid;
            int ch = idx & 15;
            int row = (idx >> 4) & 127;
            int tile = idx >> 11;
            uint32_t dst = sB[1][tile] + (row * PAD + ch * 8) * 2;
            const __half* src = ((tile == 0) ? g_bhi : g_blo)
                                + (size_t)16384 + (size_t)row * 128 + ch * 8;
            asm volatile("cp.async.cg.shared.global [%0], [%1], 16;" :: "r"(dst), "l"(src));
        }
        asm volatile("cp.async.commit_group;");
    }

    int m8  = lane >> 3;
    int arow = (m8 & 1) * 8 + (lane & 7);
    int acol = (m8 >> 1) * 8;
    int bnr  = (m8 >> 1) * 8 + (lane & 7);
    int bkc  = (m8 & 1) * 8;
    int lr = lane >> 2, lc = (lane & 3) * 2;

#pragma unroll 1
    for (int r = 0; r < NREL; r++) {
        if (r < NREL - 1) asm volatile("cp.async.wait_group 1;");
        else              asm volatile("cp.async.wait_group 0;");
        __syncthreads();

        float acc[2][8][4];
#pragma unroll
        for (int mi = 0; mi < 2; mi++)
#pragma unroll
            for (int ni = 0; ni < 8; ni++)
#pragma unroll
                for (int j = 0; j < 4; j++) acc[mi][ni][j] = 0.f;

        uint32_t bh_base = sB[r & 1][0];
        uint32_t bl_base = sB[r & 1][1];
#pragma unroll
        for (int ks = 0; ks < 8; ks++) {
            int kc = ks * 16;
            uint32_t a[2][4];
#pragma unroll
            for (int mi = 0; mi < 2; mi++) {
                uint32_t off = ((wr * 32 + mi * 16 + arow) * PAD + kc + acol) * 2;
                asm volatile("ldmatrix.sync.aligned.m8n8.x4.shared.b16 {%0,%1,%2,%3}, [%4];"
                             : "=r"(a[mi][0]), "=r"(a[mi][1]), "=r"(a[mi][2]), "=r"(a[mi][3])
                             : "r"(sA + off));
            }
            uint32_t bh[8][2], bl[8][2];
#pragma unroll
            for (int np = 0; np < 4; np++) {
                uint32_t off = ((wc * 64 + np * 16 + bnr) * PAD + kc + bkc) * 2;
                asm volatile("ldmatrix.sync.aligned.m8n8.x4.shared.b16 {%0,%1,%2,%3}, [%4];"
                             : "=r"(bh[np * 2][0]), "=r"(bh[np * 2][1]),
                               "=r"(bh[np * 2 + 1][0]), "=r"(bh[np * 2 + 1][1])
                             : "r"(bh_base + off));
                asm volatile("ldmatrix.sync.aligned.m8n8.x4.shared.b16 {%0,%1,%2,%3}, [%4];"
                             : "=r"(bl[np * 2][0]), "=r"(bl[np * 2][1]),
                               "=r"(bl[np * 2 + 1][0]), "=r"(bl[np * 2 + 1][1])
                             : "r"(bl_base + off));
            }
#pragma unroll
            for (int mi = 0; mi < 2; mi++)
#pragma unroll
                for (int ni = 0; ni < 8; ni++) {
                    MMA_F16(acc[mi][ni], a[mi], bh[ni]);
                    MMA_F16(acc[mi][ni], a[mi], bl[ni]);
                }
        }
        __syncthreads();   // all warps done reading buf (r&1) before refill

        // prefetch B[r+2] into buf (r&1)
        if (NREL > 1 && r + 2 < NREL) {
            size_t boff = (size_t)(r + 2) * 16384;
#pragma unroll
            for (int t = 0; t < 16; t++) {
                int idx = t * 256 + tid;
                int ch = idx & 15;
                int row = (idx >> 4) & 127;
                int tile = idx >> 11;
                uint32_t dst = sB[r & 1][tile] + (row * PAD + ch * 8) * 2;
                const __half* src = ((tile == 0) ? g_bhi : g_blo)
                                    + boff + (size_t)row * 128 + ch * 8;
                asm volatile("cp.async.cg.shared.global [%0], [%1], 16;" :: "r"(dst), "l"(src));
            }
            asm volatile("cp.async.commit_group;");
        }

        // epilogue for relation r
#pragma unroll
        for (int mi = 0; mi < 2; mi++) {
            int row0 = rowBase + wr * 32 + mi * 16 + lr;
#pragma unroll
            for (int ni = 0; ni < 8; ni++) {
                int col = wc * 64 + ni * 8 + lc;
                if (LIN) {
                    float b0 = bias[col], b1 = bias[col + 1];
                    if (row0 < N_NODES)
                        *(float2*)&outp[(size_t)row0 * 128 + col] =
                            make_float2(acc[mi][ni][0] + b0, acc[mi][ni][1] + b1);
                    if (row0 + 8 < N_NODES)
                        *(float2*)&outp[(size_t)(row0 + 8) * 128 + col] =
                            make_float2(acc[mi][ni][2] + b0, acc[mi][ni][3] + b1);
                } else {
                    __half* dsth = g_xWh + (size_t)r * N_NODES * 128;
                    if (row0 < N_NODES)
                        *(__half2*)&dsth[(size_t)row0 * 128 + col] =
                            __floats2half2_rn(acc[mi][ni][0], acc[mi][ni][1]);
                    if (row0 + 8 < N_NODES)
                        *(__half2*)&dsth[(size_t)(row0 + 8) * 128 + col] =
                            __floats2half2_rn(acc[mi][ni][2], acc[mi][ni][3]);
                }
            }
        }
    }
}

// ---------------- fold q/k into W ----------------
__global__ void k_wqk(const float* __restrict__ W, const float* __restrict__ q,
                      const float* __restrict__ kv, int which) {
    int idx = blockIdx.x * blockDim.x + threadIdx.x;
    if (idx >= R_REL * H_DIM) return;
    const float* w = W + (size_t)idx * H_DIM;
    float aq = 0.f, ak = 0.f;
#pragma unroll 4
    for (int h = 0; h < H_DIM; h++) { float wv = w[h]; aq += wv * q[h]; ak += wv * kv[h]; }
    if (which == 0) { g_wq[idx] = aq; g_wk[idx] = ak; }
    else            { g_wq2[idx] = aq; g_wk2[idx] = ak; }
}

// ---------------- s_q / s_k (layer 1 only) ----------------
__global__ __launch_bounds__(256) void k_sqk(const float* __restrict__ act) {
    __shared__ float swq[R_REL * H_DIM], swk[R_REL * H_DIM];
    int tid = threadIdx.x;
    for (int i = tid; i < R_REL * H_DIM; i += blockDim.x) { swq[i] = g_wq[i]; swk[i] = g_wk[i]; }
    __syncthreads();
    int n = blockIdx.x * 8 + (tid >> 5);
    int lane = tid & 31;
    if (n >= N_NODES) return;
    float4 a = *(const float4*)&act[(size_t)n * H_DIM + lane * 4];
    float accq[R_REL], acck[R_REL];
#pragma unroll
    for (int r = 0; r < R_REL; r++) {
        float4 wq4 = *(const float4*)&swq[r * H_DIM + lane * 4];
        float4 wk4 = *(const float4*)&swk[r * H_DIM + lane * 4];
        accq[r] = a.x * wq4.x + a.y * wq4.y + a.z * wq4.z + a.w * wq4.w;
        acck[r] = a.x * wk4.x + a.y * wk4.y + a.z * wk4.z + a.w * wk4.w;
    }
#pragma unroll
    for (int off = 16; off > 0; off >>= 1)
#pragma unroll
        for (int r = 0; r < R_REL; r++) {
            accq[r] += __shfl_xor_sync(0xffffffffu, accq[r], off);
            acck[r] += __shfl_xor_sync(0xffffffffu, acck[r], off);
        }
    if (lane < R_REL)            g_sq[lane * N_NODES + n] = accq[lane];
    else if (lane < 2 * R_REL)   g_sk[(lane - R_REL) * N_NODES + n] = acck[lane - R_REL];
}

// ---------------- softmax + aggregate: SINGLE PASS (no max, bounded logits) -------
template<bool FUSE, bool SRC2, bool SPLIT>
__global__ __launch_bounds__(256) void k_agg(const float* __restrict__ bias) {
    __shared__ float swq[R_REL * H_DIM], swk[R_REL * H_DIM];
    int tid = threadIdx.x;
    int lane = tid & 31;
    if (FUSE) {
        for (int i = tid; i < R_REL * H_DIM; i += 256) { swq[i] = g_wq2[i]; swk[i] = g_wk2[i]; }
        __syncthreads();
    }
    int n = blockIdx.x * 8 + (tid >> 5);
    if (n >= N_NODES) return;
    const float* SQ = SRC2 ? g_sq2 : g_sq;
    const float* SK = SRC2 ? g_sk2 : g_sk;
    int s = g_rowptr[n], e = g_rowptr[n + 1];

    float4 acc = make_float4(0.f, 0.f, 0.f, 0.f);
    float den = 1e-16f;
    int i = s;
    for (; i + 1 < e; i += 2) {
        int p0 = g_csr[i], p1 = g_csr[i + 1];
        int s0 = p0 & 0x1FFFF, r0 = p0 >> 17;
        int s1 = p1 & 0x1FFFF, r1 = p1 >> 17;
        float v0 = SQ[r0 * N_NODES + n] + SK[r0 * N_NODES + s0];
        float v1 = SQ[r1 * N_NODES + n] + SK[r1 * N_NODES + s1];
        v0 = v0 > 0.f ? v0 : 0.2f * v0;
        v1 = v1 > 0.f ? v1 : 0.2f * v1;
        float w0 = __expf(v0);
        float w1 = __expf(v1);
        den += w0 + w1;
        const __half2* ra = (const __half2*)&g_xWh[((size_t)r0 * N_NODES + s0) * 128 + lane * 4];
        const __half2* rb = (const __half2*)&g_xWh[((size_t)r1 * N_NODES + s1) * 128 + lane * 4];
        float2 a0 = __half22float2(ra[0]), a1 = __half22float2(ra[1]);
        float2 b0 = __half22float2(rb[0]), b1 = __half22float2(rb[1]);
        acc.x += w0 * a0.x + w1 * b0.x;
        acc.y += w0 * a0.y + w1 * b0.y;
        acc.z += w0 * a1.x + w1 * b1.x;
        acc.w += w0 * a1.y + w1 * b1.y;
    }
    if (i < e) {
        int p = g_csr[i]; int s0 = p & 0x1FFFF; int r = p >> 17;
        float v = SQ[r * N_NODES + n] + SK[r * N_NODES + s0];
        v = v > 0.f ? v : 0.2f * v;
        float w = __expf(v);
        den += w;
        const __half2* ra = (const __half2*)&g_xWh[((size_t)r * N_NODES + s0) * 128 + lane * 4];
        float2 a0 = __half22float2(ra[0]), a1 = __half22float2(ra[1]);
        acc.x += w * a0.x; acc.y += w * a0.y; acc.z += w * a1.x; acc.w += w * a1.y;
    }
    float inv = 1.f / den;
    float4 bv = *(const float4*)&bias[lane * 4];
    float4 o;
    o.x = fmaxf(acc.x * inv + bv.x, 0.f);
    o.y = fmaxf(acc.y * inv + bv.y, 0.f);
    o.z = fmaxf(acc.z * inv + bv.z, 0.f);
    o.w = fmaxf(acc.w * inv + bv.w, 0.f);

    if (FUSE || SPLIT) {
        __half2* p = (__half2*)&g_ah[(size_t)n * 128 + lane * 4];
        p[0] = __floats2half2_rn(o.x, o.y);
        p[1] = __floats2half2_rn(o.z, o.w);
    }
    if (FUSE) {
        float accq[R_REL], acck[R_REL];
#pragma unroll
        for (int r = 0; r < R_REL; r++) {
            float4 wq4 = *(const float4*)&swq[r * H_DIM + lane * 4];
            float4 wk4 = *(const float4*)&swk[r * H_DIM + lane * 4];
            accq[r] = o.x * wq4.x + o.y * wq4.y + o.z * wq4.z + o.w * wq4.w;
            acck[r] = o.x * wk4.x + o.y * wk4.y + o.z * wk4.z + o.w * wk4.w;
        }
#pragma unroll
        for (int off = 16; off > 0; off >>= 1)
#pragma unroll
            for (int r = 0; r < R_REL; r++) {
                accq[r] += __shfl_xor_sync(0xffffffffu, accq[r], off);
                acck[r] += __shfl_xor_sync(0xffffffffu, acck[r], off);
            }
        if (lane < R_REL)            g_sq2[lane * N_NODES + n] = accq[lane];
        else if (lane < 2 * R_REL)   g_sk2[(lane - R_REL) * N_NODES + n] = acck[lane - R_REL];
    }
}

// ---------------- launch ----------------
extern "C" void kernel_launch(void* const* d_in, const int* in_sizes, int n_in,
                              void* d_out, int out_size) {
    const float* x  = (const float*)d_in[0];
    const int*   ei = (const int*)d_in[1];
    const int*   et = (const int*)d_in[2];
    const float* W1 = (const float*)d_in[4];
    const float* q1 = (const float*)d_in[5];
    const float* k1 = (const float*)d_in[6];
    const float* b1 = (const float*)d_in[7];
    const float* W2 = (const float*)d_in[8];
    const float* q2 = (const float*)d_in[9];
    const float* k2 = (const float*)d_in[10];
    const float* b2 = (const float*)d_in[11];
    const float* Wl = (const float*)d_in[12];
    const float* bl = (const float*)d_in[13];
    float* out = (float*)d_out;
    const int* srcp = ei;
    const int* tgtp = ei + N_EDGES;

    static bool attr_done = false;
    if (!attr_done) {
        cudaFuncSetAttribute(k_hgemm<R_REL, false>,
                             cudaFuncAttributeMaxDynamicSharedMemorySize, GEMM_SMEM);
        cudaFuncSetAttribute(k_hgemm<1, true>,
                             cudaFuncAttributeMaxDynamicSharedMemorySize, GEMM_SMEM);
        attr_done = true;
    }

    dim3 gWarp((N_NODES + 7) / 8);
    int total4 = N_NODES * H_DIM / 4;

    // ordered so launch #4 (ncu capture slot) is the layer-1 HMMA GEMM
    k_zero_cnt<<<(N_NODES + 255) / 256, 256>>>();
    k_split_act<<<(total4 + 255) / 256, 256>>>(x, total4);
    k_split_W<<<(R_REL * H_DIM * H_DIM + 255) / 256, 256>>>(W1);
    k_hgemm<R_REL, false><<<ROW_TILES, 256, GEMM_SMEM>>>(nullptr, nullptr);   // #4

    // CSR build
    k_hist<<<(N_EDGES + 255) / 256, 256>>>(tgtp);
    k_scan_blk<<<SCAN_BLKS, 256>>>();
    k_scan_top<<<1, 256>>>();
    k_scan_add<<<SCAN_BLKS, 256>>>();
    k_scatter<<<(N_EDGES + 255) / 256, 256>>>(srcp, tgtp, et);

    // layer-1 attention inputs
    k_wqk<<<4, 256>>>(W1, q1, k1, 0);
    k_sqk<<<gWarp, 256>>>(x);
    k_wqk<<<4, 256>>>(W2, q2, k2, 1);
    k_agg<true, false, false><<<gWarp, 256>>>(b1);   // h1 -> g_ah + sq2/sk2

    // layer 2
    k_split_W<<<(R_REL * H_DIM * H_DIM + 255) / 256, 256>>>(W2);
    k_hgemm<R_REL, false><<<ROW_TILES, 256, GEMM_SMEM>>>(nullptr, nullptr);
    k_agg<false, true, true><<<gWarp, 256>>>(b2);    // h2 -> g_ah

    // final linear via HMMA
    k_split_Wl<<<(H_DIM * H_DIM + 255) / 256, 256>>>(Wl);
    k_hgemm<1, true><<<ROW_TILES, 256, GEMM_SMEM>>>(out, bl);
}

// round 15
// speedup vs baseline: 1.3860x; 1.3860x over previous
#include <cuda_runtime.h>
#include <cuda_bf16.h>
#include <cuda_fp16.h>
#include <cstdint>

#define N_NODES 50000
#define N_EDGES 800000
#define R_REL 8
#define H_DIM 128
#define ROW_TILES ((N_NODES + 127) / 128)
#define SCAN_BLKS ((N_NODES + 255) / 256)
#define PAD 136
#define TILE_A (128 * PAD)
#define GEMM_SMEM (6 * TILE_A * 2)

// ---------------- scratch (device globals: allocation-free) ----------------
__device__ __half g_xWh[(size_t)R_REL * N_NODES * H_DIM];  // 102.4 MB (fits L2)
__device__ float g_sq[R_REL * N_NODES];
__device__ float g_sk[R_REL * N_NODES];
__device__ float g_sq2[R_REL * N_NODES];
__device__ float g_sk2[R_REL * N_NODES];
__device__ float g_wq[R_REL * H_DIM];
__device__ float g_wk[R_REL * H_DIM];
__device__ float g_wq2[R_REL * H_DIM];
__device__ float g_wk2[R_REL * H_DIM];
__device__ float g_logit[N_EDGES];
__device__ int   g_cnt[N_NODES];
__device__ int   g_rowptr[N_NODES + 1];
__device__ int   g_cursor[N_NODES];
__device__ int   g_csr[N_EDGES];
__device__ int   g_blksum[SCAN_BLKS];
__device__ int   g_total;
// split-bf16 operands for tensor-core GEMM
__device__ __nv_bfloat16 g_ahi[(size_t)N_NODES * H_DIM];
__device__ __nv_bfloat16 g_alo[(size_t)N_NODES * H_DIM];
__device__ __nv_bfloat16 g_bhi[R_REL * H_DIM * H_DIM];    // [r][n][k] = W[r][k][n]
__device__ __nv_bfloat16 g_blo[R_REL * H_DIM * H_DIM];

__device__ __forceinline__ uint32_t smem_u32(const void* p) {
    uint32_t a;
    asm("{ .reg .u64 t; cvta.to.shared.u64 t, %1; cvt.u32.u64 %0, t; }" : "=r"(a) : "l"(p));
    return a;
}

// ---------------- CSR build ----------------
__global__ void k_zero_cnt() {
    int i = blockIdx.x * blockDim.x + threadIdx.x;
    if (i < N_NODES) g_cnt[i] = 0;
}
__global__ void k_hist(const int* __restrict__ tgt) {
    int e = blockIdx.x * blockDim.x + threadIdx.x;
    if (e < N_EDGES) atomicAdd(&g_cnt[tgt[e]], 1);
}
__global__ __launch_bounds__(256) void k_scan_blk() {
    __shared__ int sm[256];
    int tid = threadIdx.x;
    int i = blockIdx.x * 256 + tid;
    int v = (i < N_NODES) ? g_cnt[i] : 0;
    sm[tid] = v;
    __syncthreads();
#pragma unroll
    for (int off = 1; off < 256; off <<= 1) {
        int t = (tid >= off) ? sm[tid - off] : 0;
        __syncthreads();
        sm[tid] += t;
        __syncthreads();
    }
    if (i < N_NODES) g_rowptr[i] = sm[tid] - v;
    if (tid == 255) g_blksum[blockIdx.x] = sm[255];
}
__global__ __launch_bounds__(256) void k_scan_top() {
    __shared__ int sm[256];
    int tid = threadIdx.x;
    int v = (tid < SCAN_BLKS) ? g_blksum[tid] : 0;
    sm[tid] = v;
    __syncthreads();
#pragma unroll
    for (int off = 1; off < 256; off <<= 1) {
        int t = (tid >= off) ? sm[tid - off] : 0;
        __syncthreads();
        sm[tid] += t;
        __syncthreads();
    }
    if (tid < SCAN_BLKS) g_blksum[tid] = sm[tid] - v;
    if (tid == 255) g_total = sm[255];
}
__global__ __launch_bounds__(256) void k_scan_add() {
    int i = blockIdx.x * 256 + threadIdx.x;
    if (i < N_NODES) {
        int v = g_rowptr[i] + g_blksum[blockIdx.x];
        g_rowptr[i] = v;
        g_cursor[i] = v;
    }
    if (i == 0) g_rowptr[N_NODES] = g_total;
}
__global__ void k_scatter(const int* __restrict__ src, const int* __restrict__ tgt,
                          const int* __restrict__ et) {
    int e = blockIdx.x * blockDim.x + threadIdx.x;
    if (e < N_EDGES) {
        int pos = atomicAdd(&g_cursor[tgt[e]], 1);
        g_csr[pos] = (et[e] << 17) | src[e];
    }
}

// ---------------- weight splits ----------------
// B[r][n][k] = W[r][k][n], split hi/lo
__global__ void k_split_W(const float* __restrict__ W) {
    int i = blockIdx.x * blockDim.x + threadIdx.x;   // r*16384 + n*128 + k
    if (i >= R_REL * H_DIM * H_DIM) return;
    int k = i & 127, n = (i >> 7) & 127, r = i >> 14;
    float w = W[(size_t)r * 16384 + k * 128 + n];
    __nv_bfloat16 h = __float2bfloat16(w);
    g_bhi[i] = h;
    g_blo[i] = __float2bfloat16(w - __bfloat162float(h));
}
// Wl is already [out][k] — split without transpose into slot 0
__global__ void k_split_Wl(const float* __restrict__ Wl) {
    int i = blockIdx.x * blockDim.x + threadIdx.x;
    if (i >= H_DIM * H_DIM) return;
    float w = Wl[i];
    __nv_bfloat16 h = __float2bfloat16(w);
    g_bhi[i] = h;
    g_blo[i] = __float2bfloat16(w - __bfloat162float(h));
}

// ---------------- fold q/k into W (both layers, one launch) ----------------
__global__ void k_wqk_all(const float* __restrict__ W1, const float* __restrict__ q1,
                          const float* __restrict__ k1,
                          const float* __restrict__ W2, const float* __restrict__ q2,
                          const float* __restrict__ k2) {
    int idx = blockIdx.x * blockDim.x + threadIdx.x;   // 0..2047
    if (idx >= 2 * R_REL * H_DIM) return;
    int which = idx >> 10;
    int j = idx & 1023;
    const float* W = which ? W2 : W1;
    const float* q = which ? q2 : q1;
    const float* kv = which ? k2 : k1;
    const float* w = W + (size_t)j * H_DIM;
    float aq = 0.f, ak = 0.f;
#pragma unroll 4
    for (int h = 0; h < H_DIM; h++) { float wv = w[h]; aq += wv * q[h]; ak += wv * kv[h]; }
    if (which == 0) { g_wq[j] = aq; g_wk[j] = ak; }
    else            { g_wq2[j] = aq; g_wk2[j] = ak; }
}

// ---------------- s_q / s_k + bf16 split of x (fused, layer 1) ----------------
__global__ __launch_bounds__(256) void k_sqk_split(const float* __restrict__ act) {
    __shared__ float swq[R_REL * H_DIM], swk[R_REL * H_DIM];
    int tid = threadIdx.x;
    for (int i = tid; i < R_REL * H_DIM; i += blockDim.x) { swq[i] = g_wq[i]; swk[i] = g_wk[i]; }
    __syncthreads();
    int n = blockIdx.x * 8 + (tid >> 5);
    int lane = tid & 31;
    if (n >= N_NODES) return;
    float4 a = *(const float4*)&act[(size_t)n * H_DIM + lane * 4];
    // bf16 hi/lo split of x
    {
        size_t base = (size_t)n * 128 + lane * 4;
        __nv_bfloat16 h0 = __float2bfloat16(a.x), h1 = __float2bfloat16(a.y);
        __nv_bfloat16 h2 = __float2bfloat16(a.z), h3 = __float2bfloat16(a.w);
        __nv_bfloat162* ph = (__nv_bfloat162*)&g_ahi[base];
        __nv_bfloat162* pl = (__nv_bfloat162*)&g_alo[base];
        ph[0] = __nv_bfloat162(h0, h1);
        ph[1] = __nv_bfloat162(h2, h3);
        pl[0] = __nv_bfloat162(__float2bfloat16(a.x - __bfloat162float(h0)),
                               __float2bfloat16(a.y - __bfloat162float(h1)));
        pl[1] = __nv_bfloat162(__float2bfloat16(a.z - __bfloat162float(h2)),
                               __float2bfloat16(a.w - __bfloat162float(h3)));
    }
    float accq[R_REL], acck[R_REL];
#pragma unroll
    for (int r = 0; r < R_REL; r++) {
        float4 wq4 = *(const float4*)&swq[r * H_DIM + lane * 4];
        float4 wk4 = *(const float4*)&swk[r * H_DIM + lane * 4];
        accq[r] = a.x * wq4.x + a.y * wq4.y + a.z * wq4.z + a.w * wq4.w;
        acck[r] = a.x * wk4.x + a.y * wk4.y + a.z * wk4.z + a.w * wk4.w;
    }
#pragma unroll
    for (int off = 16; off > 0; off >>= 1)
#pragma unroll
        for (int r = 0; r < R_REL; r++) {
            accq[r] += __shfl_xor_sync(0xffffffffu, accq[r], off);
            acck[r] += __shfl_xor_sync(0xffffffffu, acck[r], off);
        }
    if (lane < R_REL)            g_sq[lane * N_NODES + n] = accq[lane];
    else if (lane < 2 * R_REL)   g_sk[(lane - R_REL) * N_NODES + n] = acck[lane - R_REL];
}

// ---------------- HMMA GEMM (bf16 3-term, round-13 proven): one CTA per row-tile ----
extern __shared__ __nv_bfloat16 s_dyn[];
template<int NREL, bool LIN>
__global__ __launch_bounds__(256) void k_hgemm(float* __restrict__ outp,
                                               const float* __restrict__ bias) {
    int tid = threadIdx.x;
    int wid = tid >> 5, lane = tid & 31;
    int wr = wid >> 1, wc = wid & 1;
    int rowBase = blockIdx.x * 128;

    uint32_t sA[2] = { smem_u32(&s_dyn[0]), smem_u32(&s_dyn[TILE_A]) };
    uint32_t sB[2][2] = { { smem_u32(&s_dyn[2 * TILE_A]), smem_u32(&s_dyn[3 * TILE_A]) },
                          { smem_u32(&s_dyn[4 * TILE_A]), smem_u32(&s_dyn[5 * TILE_A]) } };

#pragma unroll
    for (int t = 0; t < 16; t++) {
        int idx = t * 256 + tid;
        int ch = idx & 15;
        int row = (idx >> 4) & 127;
        int tile = idx >> 11;
        uint32_t dst = sA[tile] + (row * PAD + ch * 8) * 2;
        int gr = rowBase + row;
        const __nv_bfloat16* src = ((tile == 0) ? g_ahi : g_alo) + (size_t)gr * 128 + ch * 8;
        int sz = (gr < N_NODES) ? 16 : 0;
        asm volatile("cp.async.cg.shared.global [%0], [%1], 16, %2;"
                     :: "r"(dst), "l"(src), "r"(sz));
    }
#pragma unroll
    for (int t = 0; t < 16; t++) {
        int idx = t * 256 + tid;
        int ch = idx & 15;
        int row = (idx >> 4) & 127;
        int tile = idx >> 11;
        uint32_t dst = sB[0][tile] + (row * PAD + ch * 8) * 2;
        const __nv_bfloat16* src = ((tile == 0) ? g_bhi : g_blo) + (size_t)row * 128 + ch * 8;
        asm volatile("cp.async.cg.shared.global [%0], [%1], 16;" :: "r"(dst), "l"(src));
    }
    asm volatile("cp.async.commit_group;");
    if (NREL > 1) {
#pragma unroll
        for (int t = 0; t < 16; t++) {
            int idx = t * 256 + tid;
            int ch = idx & 15;
            int row = (idx >> 4) & 127;
            int tile = idx >> 11;
            uint32_t dst = sB[1][tile] + (row * PAD + ch * 8) * 2;
            const __nv_bfloat16* src = ((tile == 0) ? g_bhi : g_blo)
                                       + (size_t)16384 + (size_t)row * 128 + ch * 8;
            asm volatile("cp.async.cg.shared.global [%0], [%1], 16;" :: "r"(dst), "l"(src));
        }
        asm volatile("cp.async.commit_group;");
    }

    int m8  = lane >> 3;
    int arow = (m8 & 1) * 8 + (lane & 7);
    int acol = (m8 >> 1) * 8;
    int bnr  = (m8 >> 1) * 8 + (lane & 7);
    int bkc  = (m8 & 1) * 8;
    int lr = lane >> 2, lc = (lane & 3) * 2;

#pragma unroll 1
    for (int r = 0; r < NREL; r++) {
        if (r < NREL - 1) asm volatile("cp.async.wait_group 1;");
        else              asm volatile("cp.async.wait_group 0;");
        __syncthreads();

        float acc[2][8][4];
#pragma unroll
        for (int mi = 0; mi < 2; mi++)
#pragma unroll
            for (int ni = 0; ni < 8; ni++)
#pragma unroll
                for (int j = 0; j < 4; j++) acc[mi][ni][j] = 0.f;

        uint32_t bh_base = sB[r & 1][0];
        uint32_t bl_base = sB[r & 1][1];
#pragma unroll
        for (int ks = 0; ks < 8; ks++) {
            int kc = ks * 16;
            uint32_t ah[2][4], al[2][4];
#pragma unroll
            for (int mi = 0; mi < 2; mi++) {
                uint32_t off = ((wr * 32 + mi * 16 + arow) * PAD + kc + acol) * 2;
                asm volatile("ldmatrix.sync.aligned.m8n8.x4.shared.b16 {%0,%1,%2,%3}, [%4];"
                             : "=r"(ah[mi][0]), "=r"(ah[mi][1]), "=r"(ah[mi][2]), "=r"(ah[mi][3])
                             : "r"(sA[0] + off));
                asm volatile("ldmatrix.sync.aligned.m8n8.x4.shared.b16 {%0,%1,%2,%3}, [%4];"
                             : "=r"(al[mi][0]), "=r"(al[mi][1]), "=r"(al[mi][2]), "=r"(al[mi][3])
                             : "r"(sA[1] + off));
            }
            uint32_t bh[8][2], bl[8][2];
#pragma unroll
            for (int np = 0; np < 4; np++) {
                uint32_t off = ((wc * 64 + np * 16 + bnr) * PAD + kc + bkc) * 2;
                asm volatile("ldmatrix.sync.aligned.m8n8.x4.shared.b16 {%0,%1,%2,%3}, [%4];"
                             : "=r"(bh[np * 2][0]), "=r"(bh[np * 2][1]),
                               "=r"(bh[np * 2 + 1][0]), "=r"(bh[np * 2 + 1][1])
                             : "r"(bh_base + off));
                asm volatile("ldmatrix.sync.aligned.m8n8.x4.shared.b16 {%0,%1,%2,%3}, [%4];"
                             : "=r"(bl[np * 2][0]), "=r"(bl[np * 2][1]),
                               "=r"(bl[np * 2 + 1][0]), "=r"(bl[np * 2 + 1][1])
                             : "r"(bl_base + off));
            }
#pragma unroll
            for (int mi = 0; mi < 2; mi++)
#pragma unroll
                for (int ni = 0; ni < 8; ni++) {
                    asm volatile(
                        "mma.sync.aligned.m16n8k16.row.col.f32.bf16.bf16.f32 "
                        "{%0,%1,%2,%3}, {%4,%5,%6,%7}, {%8,%9}, {%0,%1,%2,%3};"
                        : "+f"(acc[mi][ni][0]), "+f"(acc[mi][ni][1]),
                          "+f"(acc[mi][ni][2]), "+f"(acc[mi][ni][3])
                        : "r"(ah[mi][0]), "r"(ah[mi][1]), "r"(ah[mi][2]), "r"(ah[mi][3]),
                          "r"(bh[ni][0]), "r"(bh[ni][1]));
                    asm volatile(
                        "mma.sync.aligned.m16n8k16.row.col.f32.bf16.bf16.f32 "
                        "{%0,%1,%2,%3}, {%4,%5,%6,%7}, {%8,%9}, {%0,%1,%2,%3};"
                        : "+f"(acc[mi][ni][0]), "+f"(acc[mi][ni][1]),
                          "+f"(acc[mi][ni][2]), "+f"(acc[mi][ni][3])
                        : "r"(ah[mi][0]), "r"(ah[mi][1]), "r"(ah[mi][2]), "r"(ah[mi][3]),
                          "r"(bl[ni][0]), "r"(bl[ni][1]));
                    asm volatile(
                        "mma.sync.aligned.m16n8k16.row.col.f32.bf16.bf16.f32 "
                        "{%0,%1,%2,%3}, {%4,%5,%6,%7}, {%8,%9}, {%0,%1,%2,%3};"
                        : "+f"(acc[mi][ni][0]), "+f"(acc[mi][ni][1]),
                          "+f"(acc[mi][ni][2]), "+f"(acc[mi][ni][3])
                        : "r"(al[mi][0]), "r"(al[mi][1]), "r"(al[mi][2]), "r"(al[mi][3]),
                          "r"(bh[ni][0]), "r"(bh[ni][1]));
                }
        }
        __syncthreads();

        if (NREL > 1 && r + 2 < NREL) {
            size_t boff = (size_t)(r + 2) * 16384;
#pragma unroll
            for (int t = 0; t < 16; t++) {
                int idx = t * 256 + tid;
                int ch = idx & 15;
                int row = (idx >> 4) & 127;
                int tile = idx >> 11;
                uint32_t dst = sB[r & 1][tile] + (row * PAD + ch * 8) * 2;
                const __nv_bfloat16* src = ((tile == 0) ? g_bhi : g_blo)
                                           + boff + (size_t)row * 128 + ch * 8;
                asm volatile("cp.async.cg.shared.global [%0], [%1], 16;" :: "r"(dst), "l"(src));
            }
            asm volatile("cp.async.commit_group;");
        }

#pragma unroll
        for (int mi = 0; mi < 2; mi++) {
            int row0 = rowBase + wr * 32 + mi * 16 + lr;
#pragma unroll
            for (int ni = 0; ni < 8; ni++) {
                int col = wc * 64 + ni * 8 + lc;
                if (LIN) {
                    float b0 = bias[col], b1 = bias[col + 1];
                    if (row0 < N_NODES)
                        *(float2*)&outp[(size_t)row0 * 128 + col] =
                            make_float2(acc[mi][ni][0] + b0, acc[mi][ni][1] + b1);
                    if (row0 + 8 < N_NODES)
                        *(float2*)&outp[(size_t)(row0 + 8) * 128 + col] =
                            make_float2(acc[mi][ni][2] + b0, acc[mi][ni][3] + b1);
                } else {
                    __half* dsth = g_xWh + (size_t)r * N_NODES * 128;
                    if (row0 < N_NODES)
                        *(__half2*)&dsth[(size_t)row0 * 128 + col] =
                            __floats2half2_rn(acc[mi][ni][0], acc[mi][ni][1]);
                    if (row0 + 8 < N_NODES)
                        *(__half2*)&dsth[(size_t)(row0 + 8) * 128 + col] =
                            __floats2half2_rn(acc[mi][ni][2], acc[mi][ni][3]);
                }
            }
        }
    }
}

// ---------------- softmax + aggregate: cached logits, 4-way unrolled gather -------
template<bool FUSE, bool SRC2, bool SPLIT>
__global__ __launch_bounds__(256) void k_agg(const float* __restrict__ bias) {
    __shared__ float swq[R_REL * H_DIM], swk[R_REL * H_DIM];
    int tid = threadIdx.x;
    int lane = tid & 31;
    if (FUSE) {
        for (int i = tid; i < R_REL * H_DIM; i += 256) { swq[i] = g_wq2[i]; swk[i] = g_wk2[i]; }
        __syncthreads();
    }
    int n = blockIdx.x * 8 + (tid >> 5);
    if (n >= N_NODES) return;
    const float* SQ = SRC2 ? g_sq2 : g_sq;
    const float* SK = SRC2 ? g_sk2 : g_sk;
    int s = g_rowptr[n], e = g_rowptr[n + 1];

    // pass 1: logits + online (max, denom) — lane-parallel for MLP
    float mx = -3.0e38f, den = 0.f;
    for (int i = s + lane; i < e; i += 32) {
        int p = g_csr[i]; int sr = p & 0x1FFFF; int r = p >> 17;
        float v = SQ[r * N_NODES + n] + SK[r * N_NODES + sr];
        v = v > 0.f ? v : 0.2f * v;
        g_logit[i] = v;
        float nm = fmaxf(mx, v);
        den = den * __expf(mx - nm) + __expf(v - nm);
        mx = nm;
    }
#pragma unroll
    for (int off = 16; off > 0; off >>= 1) {
        float m2 = __shfl_xor_sync(0xffffffffu, mx, off);
        float d2 = __shfl_xor_sync(0xffffffffu, den, off);
        float nm = fmaxf(mx, m2);
        den = den * __expf(mx - nm) + d2 * __expf(m2 - nm);
        mx = nm;
    }
    float inv = 1.f / (den + 1e-16f);

    // pass 2: weighted gather, 4 edges in flight, one 8B load per row per lane
    float4 acc = make_float4(0.f, 0.f, 0.f, 0.f);
    int i = s;
    for (; i + 3 < e; i += 4) {
        int p0 = g_csr[i], p1 = g_csr[i + 1], p2 = g_csr[i + 2], p3 = g_csr[i + 3];
        float w0 = __expf(g_logit[i]     - mx) * inv;
        float w1 = __expf(g_logit[i + 1] - mx) * inv;
        float w2 = __expf(g_logit[i + 2] - mx) * inv;
        float w3 = __expf(g_logit[i + 3] - mx) * inv;
        uint2 u0 = *(const uint2*)&g_xWh[(((size_t)(p0 >> 17)) * N_NODES + (p0 & 0x1FFFF)) * 128 + lane * 4];
        uint2 u1 = *(const uint2*)&g_xWh[(((size_t)(p1 >> 17)) * N_NODES + (p1 & 0x1FFFF)) * 128 + lane * 4];
        uint2 u2 = *(const uint2*)&g_xWh[(((size_t)(p2 >> 17)) * N_NODES + (p2 & 0x1FFFF)) * 128 + lane * 4];
        uint2 u3 = *(const uint2*)&g_xWh[(((size_t)(p3 >> 17)) * N_NODES + (p3 & 0x1FFFF)) * 128 + lane * 4];
        float2 a0 = __half22float2(*(__half2*)&u0.x), a1 = __half22float2(*(__half2*)&u0.y);
        float2 b0 = __half22float2(*(__half2*)&u1.x), b1 = __half22float2(*(__half2*)&u1.y);
        float2 c0 = __half22float2(*(__half2*)&u2.x), c1 = __half22float2(*(__half2*)&u2.y);
        float2 d0 = __half22float2(*(__half2*)&u3.x), d1 = __half22float2(*(__half2*)&u3.y);
        acc.x += w0 * a0.x + w1 * b0.x + w2 * c0.x + w3 * d0.x;
        acc.y += w0 * a0.y + w1 * b0.y + w2 * c0.y + w3 * d0.y;
        acc.z += w0 * a1.x + w1 * b1.x + w2 * c1.x + w3 * d1.x;
        acc.w += w0 * a1.y + w1 * b1.y + w2 * c1.y + w3 * d1.y;
    }
    for (; i < e; i++) {
        int p = g_csr[i];
        float w = __expf(g_logit[i] - mx) * inv;
        uint2 u = *(const uint2*)&g_xWh[(((size_t)(p >> 17)) * N_NODES + (p & 0x1FFFF)) * 128 + lane * 4];
        float2 a0 = __half22float2(*(__half2*)&u.x), a1 = __half22float2(*(__half2*)&u.y);
        acc.x += w * a0.x; acc.y += w * a0.y; acc.z += w * a1.x; acc.w += w * a1.y;
    }
    float4 bv = *(const float4*)&bias[lane * 4];
    float4 o;
    o.x = fmaxf(acc.x + bv.x, 0.f);
    o.y = fmaxf(acc.y + bv.y, 0.f);
    o.z = fmaxf(acc.z + bv.z, 0.f);
    o.w = fmaxf(acc.w + bv.w, 0.f);

    if (FUSE || SPLIT) {
        size_t base = (size_t)n * 128 + lane * 4;
        __nv_bfloat16 h0 = __float2bfloat16(o.x), h1 = __float2bfloat16(o.y);
        __nv_bfloat16 h2b = __float2bfloat16(o.z), h3 = __float2bfloat16(o.w);
        __nv_bfloat162* ph = (__nv_bfloat162*)&g_ahi[base];
        __nv_bfloat162* pl = (__nv_bfloat162*)&g_alo[base];
        ph[0] = __nv_bfloat162(h0, h1);
        ph[1] = __nv_bfloat162(h2b, h3);
        pl[0] = __nv_bfloat162(__float2bfloat16(o.x - __bfloat162float(h0)),
                               __float2bfloat16(o.y - __bfloat162float(h1)));
        pl[1] = __nv_bfloat162(__float2bfloat16(o.z - __bfloat162float(h2b)),
                               __float2bfloat16(o.w - __bfloat162float(h3)));
    }
    if (FUSE) {
        float accq[R_REL], acck[R_REL];
#pragma unroll
        for (int r = 0; r < R_REL; r++) {
            float4 wq4 = *(const float4*)&swq[r * H_DIM + lane * 4];
            float4 wk4 = *(const float4*)&swk[r * H_DIM + lane * 4];
            accq[r] = o.x * wq4.x + o.y * wq4.y + o.z * wq4.z + o.w * wq4.w;
            acck[r] = o.x * wk4.x + o.y * wk4.y + o.z * wk4.z + o.w * wk4.w;
        }
#pragma unroll
        for (int off = 16; off > 0; off >>= 1)
#pragma unroll
            for (int r = 0; r < R_REL; r++) {
                accq[r] += __shfl_xor_sync(0xffffffffu, accq[r], off);
                acck[r] += __shfl_xor_sync(0xffffffffu, acck[r], off);
            }
        if (lane < R_REL)            g_sq2[lane * N_NODES + n] = accq[lane];
        else if (lane < 2 * R_REL)   g_sk2[(lane - R_REL) * N_NODES + n] = acck[lane - R_REL];
    }
}

// ---------------- launch ----------------
extern "C" void kernel_launch(void* const* d_in, const int* in_sizes, int n_in,
                              void* d_out, int out_size) {
    const float* x  = (const float*)d_in[0];
    const int*   ei = (const int*)d_in[1];
    const int*   et = (const int*)d_in[2];
    const float* W1 = (const float*)d_in[4];
    const float* q1 = (const float*)d_in[5];
    const float* k1 = (const float*)d_in[6];
    const float* b1 = (const float*)d_in[7];
    const float* W2 = (const float*)d_in[8];
    const float* q2 = (const float*)d_in[9];
    const float* k2 = (const float*)d_in[10];
    const float* b2 = (const float*)d_in[11];
    const float* Wl = (const float*)d_in[12];
    const float* bl = (const float*)d_in[13];
    float* out = (float*)d_out;
    const int* srcp = ei;
    const int* tgtp = ei + N_EDGES;

    static bool attr_done = false;
    if (!attr_done) {
        cudaFuncSetAttribute(k_hgemm<R_REL, false>,
                             cudaFuncAttributeMaxDynamicSharedMemorySize, GEMM_SMEM);
        cudaFuncSetAttribute(k_hgemm<1, true>,
                             cudaFuncAttributeMaxDynamicSharedMemorySize, GEMM_SMEM);
        attr_done = true;
    }

    dim3 gWarp((N_NODES + 7) / 8);

    // ordered so launch #4 (ncu capture slot) is the layer-1 HMMA GEMM
    k_wqk_all<<<8, 256>>>(W1, q1, k1, W2, q2, k2);
    k_sqk_split<<<gWarp, 256>>>(x);              // splits of x + layer-1 sq/sk
    k_split_W<<<(R_REL * H_DIM * H_DIM + 255) / 256, 256>>>(W1);
    k_hgemm<R_REL, false><<<ROW_TILES, 256, GEMM_SMEM>>>(nullptr, nullptr);   // #4

    // CSR build
    k_zero_cnt<<<(N_NODES + 255) / 256, 256>>>();
    k_hist<<<(N_EDGES + 255) / 256, 256>>>(tgtp);
    k_scan_blk<<<SCAN_BLKS, 256>>>();
    k_scan_top<<<1, 256>>>();
    k_scan_add<<<SCAN_BLKS, 256>>>();
    k_scatter<<<(N_EDGES + 255) / 256, 256>>>(srcp, tgtp, et);

    // layer-1 attention + aggregate
    k_agg<true, false, false><<<gWarp, 256>>>(b1);   // h1 -> splits + sq2/sk2

    // layer 2
    k_split_W<<<(R_REL * H_DIM * H_DIM + 255) / 256, 256>>>(W2);
    k_hgemm<R_REL, false><<<ROW_TILES, 256, GEMM_SMEM>>>(nullptr, nullptr);
    k_agg<false, true, true><<<gWarp, 256>>>(b2);    // h2 -> splits

    // final linear via HMMA
    k_split_Wl<<<(H_DIM * H_DIM + 255) / 256, 256>>>(Wl);
    k_hgemm<1, true><<<ROW_TILES, 256, GEMM_SMEM>>>(out, bl);
}

// round 16
// speedup vs baseline: 1.4612x; 1.0543x over previous
#include <cuda_runtime.h>
#include <cuda_bf16.h>
#include <cuda_fp16.h>
#include <cstdint>

#define N_NODES 50000
#define N_EDGES 800000
#define R_REL 8
#define H_DIM 128
#define ROW_TILES ((N_NODES + 127) / 128)
#define SCAN_BLKS ((N_NODES + 255) / 256)
#define PAD 136
#define TILE_A (128 * PAD)
#define GEMM_SMEM (6 * TILE_A * 2)

// ---------------- scratch (device globals: allocation-free) ----------------
__device__ __half g_xWh[(size_t)R_REL * N_NODES * H_DIM];  // 102.4 MB (fits L2)
__device__ float g_sq[R_REL * N_NODES];
__device__ float g_sk[R_REL * N_NODES];
__device__ float g_sq2[R_REL * N_NODES];
__device__ float g_sk2[R_REL * N_NODES];
__device__ float g_wq[R_REL * H_DIM];
__device__ float g_wk[R_REL * H_DIM];
__device__ float g_wq2[R_REL * H_DIM];
__device__ float g_wk2[R_REL * H_DIM];
__device__ float g_logit[N_EDGES];
__device__ int   g_cnt[N_NODES];
__device__ int   g_rowptr[N_NODES + 1];
__device__ int   g_cursor[N_NODES];
__device__ int   g_csr[N_EDGES];
__device__ int   g_blksum[SCAN_BLKS];
__device__ int   g_total;
// split-bf16 operands (separate buffer sets per GEMM so splits can run early)
__device__ __nv_bfloat16 g_ahi[(size_t)N_NODES * H_DIM];
__device__ __nv_bfloat16 g_alo[(size_t)N_NODES * H_DIM];
__device__ __nv_bfloat16 g_bhi[R_REL * H_DIM * H_DIM];
__device__ __nv_bfloat16 g_blo[R_REL * H_DIM * H_DIM];
__device__ __nv_bfloat16 g_bhi2[R_REL * H_DIM * H_DIM];
__device__ __nv_bfloat16 g_blo2[R_REL * H_DIM * H_DIM];
__device__ __nv_bfloat16 g_bhiL[H_DIM * H_DIM];
__device__ __nv_bfloat16 g_bloL[H_DIM * H_DIM];

__device__ __forceinline__ uint32_t smem_u32(const void* p) {
    uint32_t a;
    asm("{ .reg .u64 t; cvta.to.shared.u64 t, %1; cvt.u32.u64 %0, t; }" : "=r"(a) : "l"(p));
    return a;
}

// ---------------- CSR build ----------------
__global__ void k_zero_cnt() {
    int i = blockIdx.x * blockDim.x + threadIdx.x;
    if (i < N_NODES) g_cnt[i] = 0;
}
__global__ void k_hist(const int* __restrict__ tgt) {
    int e = blockIdx.x * blockDim.x + threadIdx.x;
    if (e < N_EDGES) atomicAdd(&g_cnt[tgt[e]], 1);
}
__global__ __launch_bounds__(256) void k_scan_blk() {
    __shared__ int sm[256];
    int tid = threadIdx.x;
    int i = blockIdx.x * 256 + tid;
    int v = (i < N_NODES) ? g_cnt[i] : 0;
    sm[tid] = v;
    __syncthreads();
#pragma unroll
    for (int off = 1; off < 256; off <<= 1) {
        int t = (tid >= off) ? sm[tid - off] : 0;
        __syncthreads();
        sm[tid] += t;
        __syncthreads();
    }
    if (i < N_NODES) g_rowptr[i] = sm[tid] - v;
    if (tid == 255) g_blksum[blockIdx.x] = sm[255];
}
__global__ __launch_bounds__(256) void k_scan_top() {
    __shared__ int sm[256];
    int tid = threadIdx.x;
    int v = (tid < SCAN_BLKS) ? g_blksum[tid] : 0;
    sm[tid] = v;
    __syncthreads();
#pragma unroll
    for (int off = 1; off < 256; off <<= 1) {
        int t = (tid >= off) ? sm[tid - off] : 0;
        __syncthreads();
        sm[tid] += t;
        __syncthreads();
    }
    if (tid < SCAN_BLKS) g_blksum[tid] = sm[tid] - v;
    if (tid == 255) g_total = sm[255];
}
__global__ __launch_bounds__(256) void k_scan_add() {
    int i = blockIdx.x * 256 + threadIdx.x;
    if (i < N_NODES) {
        int v = g_rowptr[i] + g_blksum[blockIdx.x];
        g_rowptr[i] = v;
        g_cursor[i] = v;
    }
    if (i == 0) g_rowptr[N_NODES] = g_total;
}
__global__ void k_scatter(const int* __restrict__ src, const int* __restrict__ tgt,
                          const int* __restrict__ et) {
    int e = blockIdx.x * blockDim.x + threadIdx.x;
    if (e < N_EDGES) {
        int pos = atomicAdd(&g_cursor[tgt[e]], 1);
        g_csr[pos] = (et[e] << 17) | src[e];
    }
}

// ---------------- weight splits (dest selected in-kernel) ----------------
__global__ void k_split_W(const float* __restrict__ W, int which) {
    int i = blockIdx.x * blockDim.x + threadIdx.x;
    if (i >= R_REL * H_DIM * H_DIM) return;
    int k = i & 127, n = (i >> 7) & 127, r = i >> 14;
    float w = W[(size_t)r * 16384 + k * 128 + n];
    __nv_bfloat16 h = __float2bfloat16(w);
    __nv_bfloat16 l = __float2bfloat16(w - __bfloat162float(h));
    if (which == 0) { g_bhi[i] = h; g_blo[i] = l; }
    else            { g_bhi2[i] = h; g_blo2[i] = l; }
}
__global__ void k_split_Wl(const float* __restrict__ Wl) {
    int i = blockIdx.x * blockDim.x + threadIdx.x;
    if (i >= H_DIM * H_DIM) return;
    float w = Wl[i];
    __nv_bfloat16 h = __float2bfloat16(w);
    g_bhiL[i] = h;
    g_bloL[i] = __float2bfloat16(w - __bfloat162float(h));
}

// ---------------- fold q/k into W (both layers, one launch) ----------------
__global__ void k_wqk_all(const float* __restrict__ W1, const float* __restrict__ q1,
                          const float* __restrict__ k1,
                          const float* __restrict__ W2, const float* __restrict__ q2,
                          const float* __restrict__ k2) {
    int idx = blockIdx.x * blockDim.x + threadIdx.x;
    if (idx >= 2 * R_REL * H_DIM) return;
    int which = idx >> 10;
    int j = idx & 1023;
    const float* W = which ? W2 : W1;
    const float* q = which ? q2 : q1;
    const float* kv = which ? k2 : k1;
    const float* w = W + (size_t)j * H_DIM;
    float aq = 0.f, ak = 0.f;
#pragma unroll 4
    for (int h = 0; h < H_DIM; h++) { float wv = w[h]; aq += wv * q[h]; ak += wv * kv[h]; }
    if (which == 0) { g_wq[j] = aq; g_wk[j] = ak; }
    else            { g_wq2[j] = aq; g_wk2[j] = ak; }
}

// ---------------- s_q / s_k + bf16 split of x (fused, layer 1) ----------------
__global__ __launch_bounds__(256) void k_sqk_split(const float* __restrict__ act) {
    __shared__ float swq[R_REL * H_DIM], swk[R_REL * H_DIM];
    int tid = threadIdx.x;
    for (int i = tid; i < R_REL * H_DIM; i += blockDim.x) { swq[i] = g_wq[i]; swk[i] = g_wk[i]; }
    __syncthreads();
    int n = blockIdx.x * 8 + (tid >> 5);
    int lane = tid & 31;
    if (n >= N_NODES) return;
    float4 a = *(const float4*)&act[(size_t)n * H_DIM + lane * 4];
    {
        size_t base = (size_t)n * 128 + lane * 4;
        __nv_bfloat16 h0 = __float2bfloat16(a.x), h1 = __float2bfloat16(a.y);
        __nv_bfloat16 h2 = __float2bfloat16(a.z), h3 = __float2bfloat16(a.w);
        __nv_bfloat162* ph = (__nv_bfloat162*)&g_ahi[base];
        __nv_bfloat162* pl = (__nv_bfloat162*)&g_alo[base];
        ph[0] = __nv_bfloat162(h0, h1);
        ph[1] = __nv_bfloat162(h2, h3);
        pl[0] = __nv_bfloat162(__float2bfloat16(a.x - __bfloat162float(h0)),
                               __float2bfloat16(a.y - __bfloat162float(h1)));
        pl[1] = __nv_bfloat162(__float2bfloat16(a.z - __bfloat162float(h2)),
                               __float2bfloat16(a.w - __bfloat162float(h3)));
    }
    float accq[R_REL], acck[R_REL];
#pragma unroll
    for (int r = 0; r < R_REL; r++) {
        float4 wq4 = *(const float4*)&swq[r * H_DIM + lane * 4];
        float4 wk4 = *(const float4*)&swk[r * H_DIM + lane * 4];
        accq[r] = a.x * wq4.x + a.y * wq4.y + a.z * wq4.z + a.w * wq4.w;
        acck[r] = a.x * wk4.x + a.y * wk4.y + a.z * wk4.z + a.w * wk4.w;
    }
#pragma unroll
    for (int off = 16; off > 0; off >>= 1)
#pragma unroll
        for (int r = 0; r < R_REL; r++) {
            accq[r] += __shfl_xor_sync(0xffffffffu, accq[r], off);
            acck[r] += __shfl_xor_sync(0xffffffffu, acck[r], off);
        }
    if (lane < R_REL)            g_sq[lane * N_NODES + n] = accq[lane];
    else if (lane < 2 * R_REL)   g_sk[(lane - R_REL) * N_NODES + n] = acck[lane - R_REL];
}

// ---------------- HMMA GEMM (bf16 3-term): one CTA per row-tile, BSEL picks B ----
extern __shared__ __nv_bfloat16 s_dyn[];
template<int NREL, bool LIN, int BSEL>
__global__ __launch_bounds__(256) void k_hgemm(float* __restrict__ outp,
                                               const float* __restrict__ bias) {
    int tid = threadIdx.x;
    int wid = tid >> 5, lane = tid & 31;
    int wr = wid >> 1, wc = wid & 1;
    int rowBase = blockIdx.x * 128;

    const __nv_bfloat16* gbh = (BSEL == 0) ? g_bhi : (BSEL == 1) ? g_bhi2 : g_bhiL;
    const __nv_bfloat16* gbl = (BSEL == 0) ? g_blo : (BSEL == 1) ? g_blo2 : g_bloL;

    uint32_t sA[2] = { smem_u32(&s_dyn[0]), smem_u32(&s_dyn[TILE_A]) };
    uint32_t sB[2][2] = { { smem_u32(&s_dyn[2 * TILE_A]), smem_u32(&s_dyn[3 * TILE_A]) },
                          { smem_u32(&s_dyn[4 * TILE_A]), smem_u32(&s_dyn[5 * TILE_A]) } };

#pragma unroll
    for (int t = 0; t < 16; t++) {
        int idx = t * 256 + tid;
        int ch = idx & 15;
        int row = (idx >> 4) & 127;
        int tile = idx >> 11;
        uint32_t dst = sA[tile] + (row * PAD + ch * 8) * 2;
        int gr = rowBase + row;
        const __nv_bfloat16* src = ((tile == 0) ? g_ahi : g_alo) + (size_t)gr * 128 + ch * 8;
        int sz = (gr < N_NODES) ? 16 : 0;
        asm volatile("cp.async.cg.shared.global [%0], [%1], 16, %2;"
                     :: "r"(dst), "l"(src), "r"(sz));
    }
#pragma unroll
    for (int t = 0; t < 16; t++) {
        int idx = t * 256 + tid;
        int ch = idx & 15;
        int row = (idx >> 4) & 127;
        int tile = idx >> 11;
        uint32_t dst = sB[0][tile] + (row * PAD + ch * 8) * 2;
        const __nv_bfloat16* src = ((tile == 0) ? gbh : gbl) + (size_t)row * 128 + ch * 8;
        asm volatile("cp.async.cg.shared.global [%0], [%1], 16;" :: "r"(dst), "l"(src));
    }
    asm volatile("cp.async.commit_group;");
    if (NREL > 1) {
#pragma unroll
        for (int t = 0; t < 16; t++) {
            int idx = t * 256 + tid;
            int ch = idx & 15;
            int row = (idx >> 4) & 127;
            int tile = idx >> 11;
            uint32_t dst = sB[1][tile] + (row * PAD + ch * 8) * 2;
            const __nv_bfloat16* src = ((tile == 0) ? gbh : gbl)
                                       + (size_t)16384 + (size_t)row * 128 + ch * 8;
            asm volatile("cp.async.cg.shared.global [%0], [%1], 16;" :: "r"(dst), "l"(src));
        }
        asm volatile("cp.async.commit_group;");
    }

    int m8  = lane >> 3;
    int arow = (m8 & 1) * 8 + (lane & 7);
    int acol = (m8 >> 1) * 8;
    int bnr  = (m8 >> 1) * 8 + (lane & 7);
    int bkc  = (m8 & 1) * 8;
    int lr = lane >> 2, lc = (lane & 3) * 2;

#pragma unroll 1
    for (int r = 0; r < NREL; r++) {
        if (r < NREL - 1) asm volatile("cp.async.wait_group 1;");
        else              asm volatile("cp.async.wait_group 0;");
        __syncthreads();

        float acc[2][8][4];
#pragma unroll
        for (int mi = 0; mi < 2; mi++)
#pragma unroll
            for (int ni = 0; ni < 8; ni++)
#pragma unroll
                for (int j = 0; j < 4; j++) acc[mi][ni][j] = 0.f;

        uint32_t bh_base = sB[r & 1][0];
        uint32_t bl_base = sB[r & 1][1];
#pragma unroll
        for (int ks = 0; ks < 8; ks++) {
            int kc = ks * 16;
            uint32_t ah[2][4], al[2][4];
#pragma unroll
            for (int mi = 0; mi < 2; mi++) {
                uint32_t off = ((wr * 32 + mi * 16 + arow) * PAD + kc + acol) * 2;
                asm volatile("ldmatrix.sync.aligned.m8n8.x4.shared.b16 {%0,%1,%2,%3}, [%4];"
                             : "=r"(ah[mi][0]), "=r"(ah[mi][1]), "=r"(ah[mi][2]), "=r"(ah[mi][3])
                             : "r"(sA[0] + off));
                asm volatile("ldmatrix.sync.aligned.m8n8.x4.shared.b16 {%0,%1,%2,%3}, [%4];"
                             : "=r"(al[mi][0]), "=r"(al[mi][1]), "=r"(al[mi][2]), "=r"(al[mi][3])
                             : "r"(sA[1] + off));
            }
            uint32_t bh[8][2], bl[8][2];
#pragma unroll
            for (int np = 0; np < 4; np++) {
                uint32_t off = ((wc * 64 + np * 16 + bnr) * PAD + kc + bkc) * 2;
                asm volatile("ldmatrix.sync.aligned.m8n8.x4.shared.b16 {%0,%1,%2,%3}, [%4];"
                             : "=r"(bh[np * 2][0]), "=r"(bh[np * 2][1]),
                               "=r"(bh[np * 2 + 1][0]), "=r"(bh[np * 2 + 1][1])
                             : "r"(bh_base + off));
                asm volatile("ldmatrix.sync.aligned.m8n8.x4.shared.b16 {%0,%1,%2,%3}, [%4];"
                             : "=r"(bl[np * 2][0]), "=r"(bl[np * 2][1]),
                               "=r"(bl[np * 2 + 1][0]), "=r"(bl[np * 2 + 1][1])
                             : "r"(bl_base + off));
            }
#pragma unroll
            for (int mi = 0; mi < 2; mi++)
#pragma unroll
                for (int ni = 0; ni < 8; ni++) {
                    asm volatile(
                        "mma.sync.aligned.m16n8k16.row.col.f32.bf16.bf16.f32 "
                        "{%0,%1,%2,%3}, {%4,%5,%6,%7}, {%8,%9}, {%0,%1,%2,%3};"
                        : "+f"(acc[mi][ni][0]), "+f"(acc[mi][ni][1]),
                          "+f"(acc[mi][ni][2]), "+f"(acc[mi][ni][3])
                        : "r"(ah[mi][0]), "r"(ah[mi][1]), "r"(ah[mi][2]), "r"(ah[mi][3]),
                          "r"(bh[ni][0]), "r"(bh[ni][1]));
                    asm volatile(
                        "mma.sync.aligned.m16n8k16.row.col.f32.bf16.bf16.f32 "
                        "{%0,%1,%2,%3}, {%4,%5,%6,%7}, {%8,%9}, {%0,%1,%2,%3};"
                        : "+f"(acc[mi][ni][0]), "+f"(acc[mi][ni][1]),
                          "+f"(acc[mi][ni][2]), "+f"(acc[mi][ni][3])
                        : "r"(ah[mi][0]), "r"(ah[mi][1]), "r"(ah[mi][2]), "r"(ah[mi][3]),
                          "r"(bl[ni][0]), "r"(bl[ni][1]));
                    asm volatile(
                        "mma.sync.aligned.m16n8k16.row.col.f32.bf16.bf16.f32 "
                        "{%0,%1,%2,%3}, {%4,%5,%6,%7}, {%8,%9}, {%0,%1,%2,%3};"
                        : "+f"(acc[mi][ni][0]), "+f"(acc[mi][ni][1]),
                          "+f"(acc[mi][ni][2]), "+f"(acc[mi][ni][3])
                        : "r"(al[mi][0]), "r"(al[mi][1]), "r"(al[mi][2]), "r"(al[mi][3]),
                          "r"(bh[ni][0]), "r"(bh[ni][1]));
                }
        }
        __syncthreads();

        if (NREL > 1 && r + 2 < NREL) {
            size_t boff = (size_t)(r + 2) * 16384;
#pragma unroll
            for (int t = 0; t < 16; t++) {
                int idx = t * 256 + tid;
                int ch = idx & 15;
                int row = (idx >> 4) & 127;
                int tile = idx >> 11;
                uint32_t dst = sB[r & 1][tile] + (row * PAD + ch * 8) * 2;
                const __nv_bfloat16* src = ((tile == 0) ? gbh : gbl)
                                           + boff + (size_t)row * 128 + ch * 8;
                asm volatile("cp.async.cg.shared.global [%0], [%1], 16;" :: "r"(dst), "l"(src));
            }
            asm volatile("cp.async.commit_group;");
        }

#pragma unroll
        for (int mi = 0; mi < 2; mi++) {
            int row0 = rowBase + wr * 32 + mi * 16 + lr;
#pragma unroll
            for (int ni = 0; ni < 8; ni++) {
                int col = wc * 64 + ni * 8 + lc;
                if (LIN) {
                    float b0 = bias[col], b1 = bias[col + 1];
                    if (row0 < N_NODES)
                        *(float2*)&outp[(size_t)row0 * 128 + col] =
                            make_float2(acc[mi][ni][0] + b0, acc[mi][ni][1] + b1);
                    if (row0 + 8 < N_NODES)
                        *(float2*)&outp[(size_t)(row0 + 8) * 128 + col] =
                            make_float2(acc[mi][ni][2] + b0, acc[mi][ni][3] + b1);
                } else {
                    __half* dsth = g_xWh + (size_t)r * N_NODES * 128;
                    if (row0 < N_NODES)
                        *(__half2*)&dsth[(size_t)row0 * 128 + col] =
                            __floats2half2_rn(acc[mi][ni][0], acc[mi][ni][1]);
                    if (row0 + 8 < N_NODES)
                        *(__half2*)&dsth[(size_t)(row0 + 8) * 128 + col] =
                            __floats2half2_rn(acc[mi][ni][2], acc[mi][ni][3]);
                }
            }
        }
    }
}

// ---------------- softmax + aggregate: cached logits, 4-way unrolled gather -------
template<bool FUSE, bool SRC2, bool SPLIT>
__global__ __launch_bounds__(256) void k_agg(const float* __restrict__ bias) {
    __shared__ float swq[R_REL * H_DIM], swk[R_REL * H_DIM];
    int tid = threadIdx.x;
    int lane = tid & 31;
    if (FUSE) {
        for (int i = tid; i < R_REL * H_DIM; i += 256) { swq[i] = g_wq2[i]; swk[i] = g_wk2[i]; }
        __syncthreads();
    }
    int n = blockIdx.x * 8 + (tid >> 5);
    if (n >= N_NODES) return;
    const float* SQ = SRC2 ? g_sq2 : g_sq;
    const float* SK = SRC2 ? g_sk2 : g_sk;
    int s = g_rowptr[n], e = g_rowptr[n + 1];

    float mx = -3.0e38f, den = 0.f;
    for (int i = s + lane; i < e; i += 32) {
        int p = g_csr[i]; int sr = p & 0x1FFFF; int r = p >> 17;
        float v = SQ[r * N_NODES + n] + SK[r * N_NODES + sr];
        v = v > 0.f ? v : 0.2f * v;
        g_logit[i] = v;
        float nm = fmaxf(mx, v);
        den = den * __expf(mx - nm) + __expf(v - nm);
        mx = nm;
    }
#pragma unroll
    for (int off = 16; off > 0; off >>= 1) {
        float m2 = __shfl_xor_sync(0xffffffffu, mx, off);
        float d2 = __shfl_xor_sync(0xffffffffu, den, off);
        float nm = fmaxf(mx, m2);
        den = den * __expf(mx - nm) + d2 * __expf(m2 - nm);
        mx = nm;
    }
    float inv = 1.f / (den + 1e-16f);

    float4 acc = make_float4(0.f, 0.f, 0.f, 0.f);
    int i = s;
    for (; i + 3 < e; i += 4) {
        int p0 = g_csr[i], p1 = g_csr[i + 1], p2 = g_csr[i + 2], p3 = g_csr[i + 3];
        float w0 = __expf(g_logit[i]     - mx) * inv;
        float w1 = __expf(g_logit[i + 1] - mx) * inv;
        float w2 = __expf(g_logit[i + 2] - mx) * inv;
        float w3 = __expf(g_logit[i + 3] - mx) * inv;
        uint2 u0 = *(const uint2*)&g_xWh[(((size_t)(p0 >> 17)) * N_NODES + (p0 & 0x1FFFF)) * 128 + lane * 4];
        uint2 u1 = *(const uint2*)&g_xWh[(((size_t)(p1 >> 17)) * N_NODES + (p1 & 0x1FFFF)) * 128 + lane * 4];
        uint2 u2 = *(const uint2*)&g_xWh[(((size_t)(p2 >> 17)) * N_NODES + (p2 & 0x1FFFF)) * 128 + lane * 4];
        uint2 u3 = *(const uint2*)&g_xWh[(((size_t)(p3 >> 17)) * N_NODES + (p3 & 0x1FFFF)) * 128 + lane * 4];
        float2 a0 = __half22float2(*(__half2*)&u0.x), a1 = __half22float2(*(__half2*)&u0.y);
        float2 b0 = __half22float2(*(__half2*)&u1.x), b1 = __half22float2(*(__half2*)&u1.y);
        float2 c0 = __half22float2(*(__half2*)&u2.x), c1 = __half22float2(*(__half2*)&u2.y);
        float2 d0 = __half22float2(*(__half2*)&u3.x), d1 = __half22float2(*(__half2*)&u3.y);
        acc.x += w0 * a0.x + w1 * b0.x + w2 * c0.x + w3 * d0.x;
        acc.y += w0 * a0.y + w1 * b0.y + w2 * c0.y + w3 * d0.y;
        acc.z += w0 * a1.x + w1 * b1.x + w2 * c1.x + w3 * d1.x;
        acc.w += w0 * a1.y + w1 * b1.y + w2 * c1.y + w3 * d1.y;
    }
    for (; i < e; i++) {
        int p = g_csr[i];
        float w = __expf(g_logit[i] - mx) * inv;
        uint2 u = *(const uint2*)&g_xWh[(((size_t)(p >> 17)) * N_NODES + (p & 0x1FFFF)) * 128 + lane * 4];
        float2 a0 = __half22float2(*(__half2*)&u.x), a1 = __half22float2(*(__half2*)&u.y);
        acc.x += w * a0.x; acc.y += w * a0.y; acc.z += w * a1.x; acc.w += w * a1.y;
    }
    float4 bv = *(const float4*)&bias[lane * 4];
    float4 o;
    o.x = fmaxf(acc.x + bv.x, 0.f);
    o.y = fmaxf(acc.y + bv.y, 0.f);
    o.z = fmaxf(acc.z + bv.z, 0.f);
    o.w = fmaxf(acc.w + bv.w, 0.f);

    if (FUSE || SPLIT) {
        size_t base = (size_t)n * 128 + lane * 4;
        __nv_bfloat16 h0 = __float2bfloat16(o.x), h1 = __float2bfloat16(o.y);
        __nv_bfloat16 h2b = __float2bfloat16(o.z), h3 = __float2bfloat16(o.w);
        __nv_bfloat162* ph = (__nv_bfloat162*)&g_ahi[base];
        __nv_bfloat162* pl = (__nv_bfloat162*)&g_alo[base];
        ph[0] = __nv_bfloat162(h0, h1);
        ph[1] = __nv_bfloat162(h2b, h3);
        pl[0] = __nv_bfloat162(__float2bfloat16(o.x - __bfloat162float(h0)),
                               __float2bfloat16(o.y - __bfloat162float(h1)));
        pl[1] = __nv_bfloat162(__float2bfloat16(o.z - __bfloat162float(h2b)),
                               __float2bfloat16(o.w - __bfloat162float(h3)));
    }
    if (FUSE) {
        float accq[R_REL], acck[R_REL];
#pragma unroll
        for (int r = 0; r < R_REL; r++) {
            float4 wq4 = *(const float4*)&swq[r * H_DIM + lane * 4];
            float4 wk4 = *(const float4*)&swk[r * H_DIM + lane * 4];
            accq[r] = o.x * wq4.x + o.y * wq4.y + o.z * wq4.z + o.w * wq4.w;
            acck[r] = o.x * wk4.x + o.y * wk4.y + o.z * wk4.z + o.w * wk4.w;
        }
#pragma unroll
        for (int off = 16; off > 0; off >>= 1)
#pragma unroll
            for (int r = 0; r < R_REL; r++) {
                accq[r] += __shfl_xor_sync(0xffffffffu, accq[r], off);
                acck[r] += __shfl_xor_sync(0xffffffffu, acck[r], off);
            }
        if (lane < R_REL)            g_sq2[lane * N_NODES + n] = accq[lane];
        else if (lane < 2 * R_REL)   g_sk2[(lane - R_REL) * N_NODES + n] = acck[lane - R_REL];
    }
}

// ---------------- launch (two-stream overlap via event fork/join) ----------------
extern "C" void kernel_launch(void* const* d_in, const int* in_sizes, int n_in,
                              void* d_out, int out_size) {
    const float* x  = (const float*)d_in[0];
    const int*   ei = (const int*)d_in[1];
    const int*   et = (const int*)d_in[2];
    const float* W1 = (const float*)d_in[4];
    const float* q1 = (const float*)d_in[5];
    const float* k1 = (const float*)d_in[6];
    const float* b1 = (const float*)d_in[7];
    const float* W2 = (const float*)d_in[8];
    const float* q2 = (const float*)d_in[9];
    const float* k2 = (const float*)d_in[10];
    const float* b2 = (const float*)d_in[11];
    const float* Wl = (const float*)d_in[12];
    const float* bl = (const float*)d_in[13];
    float* out = (float*)d_out;
    const int* srcp = ei;
    const int* tgtp = ei + N_EDGES;

    static cudaStream_t s1 = nullptr;
    static cudaEvent_t evFork = nullptr, evJoin = nullptr;
    static bool init_done = false;
    if (!init_done) {
        cudaFuncSetAttribute(k_hgemm<R_REL, false, 0>,
                             cudaFuncAttributeMaxDynamicSharedMemorySize, GEMM_SMEM);
        cudaFuncSetAttribute(k_hgemm<R_REL, false, 1>,
                             cudaFuncAttributeMaxDynamicSharedMemorySize, GEMM_SMEM);
        cudaFuncSetAttribute(k_hgemm<1, true, 2>,
                             cudaFuncAttributeMaxDynamicSharedMemorySize, GEMM_SMEM);
        cudaStreamCreateWithFlags(&s1, cudaStreamNonBlocking);
        cudaEventCreateWithFlags(&evFork, cudaEventDisableTiming);
        cudaEventCreateWithFlags(&evJoin, cudaEventDisableTiming);
        init_done = true;
    }

    dim3 gWarp((N_NODES + 7) / 8);

    // fork side stream from main stream
    cudaEventRecord(evFork, 0);
    cudaStreamWaitEvent(s1, evFork, 0);

    // main chain: layer-1 GEMM path (hgemm1 = 4th kernel launch for ncu)
    k_wqk_all<<<8, 256>>>(W1, q1, k1, W2, q2, k2);
    k_sqk_split<<<gWarp, 256>>>(x);
    k_split_W<<<(R_REL * H_DIM * H_DIM + 255) / 256, 256>>>(W1, 0);
    k_hgemm<R_REL, false, 0><<<ROW_TILES, 256, GEMM_SMEM>>>(nullptr, nullptr);

    // side stream: CSR build + layer-2/final weight splits (all independent)
    k_zero_cnt<<<(N_NODES + 255) / 256, 256, 0, s1>>>();
    k_hist<<<(N_EDGES + 255) / 256, 256, 0, s1>>>(tgtp);
    k_scan_blk<<<SCAN_BLKS, 256, 0, s1>>>();
    k_scan_top<<<1, 256, 0, s1>>>();
    k_scan_add<<<SCAN_BLKS, 256, 0, s1>>>();
    k_scatter<<<(N_EDGES + 255) / 256, 256, 0, s1>>>(srcp, tgtp, et);
    k_split_W<<<(R_REL * H_DIM * H_DIM + 255) / 256, 256, 0, s1>>>(W2, 1);
    k_split_Wl<<<(H_DIM * H_DIM + 255) / 256, 256, 0, s1>>>(Wl);
    cudaEventRecord(evJoin, s1);

    // join before anything that needs CSR / layer-2 weights
    cudaStreamWaitEvent(0, evJoin, 0);

    // layer-1 attention + aggregate
    k_agg<true, false, false><<<gWarp, 256>>>(b1);   // h1 -> splits + sq2/sk2

    // layer 2
    k_hgemm<R_REL, false, 1><<<ROW_TILES, 256, GEMM_SMEM>>>(nullptr, nullptr);
    k_agg<false, true, true><<<gWarp, 256>>>(b2);    // h2 -> splits

    // final linear
    k_hgemm<1, true, 2><<<ROW_TILES, 256, GEMM_SMEM>>>(out, bl);
}